// round 7
// baseline (speedup 1.0000x reference)
#include <cuda_runtime.h>
#include <cuda_fp16.h>
#include <cstdint>

// ---------------- problem constants ----------------
static constexpr int TOKENS = 4096;
static constexpr int IN_F   = 4096;
static constexpr int OUT_F  = 11008;

static constexpr int BM = 128;
static constexpr int BN = 128;
static constexpr int BKB = 128;        // 128 int8 = 128 bytes per row (SW128 atom row)
static constexpr int STAGES = 3;

static constexpr int M_TILES = TOKENS / BM;    // 32
static constexpr int N_TILES = OUT_F / BN;     // 86
static constexpr int K_TILES = IN_F / BKB;     // 32

static constexpr int TILE_BYTES = 128 * BKB;        // 16384 (A tile == B tile)
static constexpr int STAGE_BYTES = 2 * TILE_BYTES;  // 32768
static constexpr int SMEM_BYTES = STAGES * STAGE_BYTES; // 98304

// ---------------- device scratch (no cudaMalloc allowed) ----------------
__device__ __align__(1024) uint8_t g_xhi[(size_t)M_TILES * K_TILES * TILE_BYTES]; // 16.8 MB
__device__ __align__(1024) uint8_t g_xlo[(size_t)M_TILES * K_TILES * TILE_BYTES]; // 16.8 MB
__device__ __align__(1024) uint8_t g_wq [(size_t)N_TILES * K_TILES * TILE_BYTES]; // 45 MB
__device__ float g_T[TOKENS];     // per-row sum of x16 (exact, as float)
__device__ float g_invQ[TOKENS];  // per-row 1/Q

// ---------------- helpers ----------------
__device__ __forceinline__ uint32_t smem_u32(const void* p) {
    uint32_t a;
    asm("{ .reg .u64 t; cvta.to.shared.u64 t, %1; cvt.u32.u64 %0, t; }" : "=r"(a) : "l"(p));
    return a;
}
__device__ __forceinline__ uint32_t swz(uint32_t off) { return off ^ ((off >> 3) & 0x70); }

__device__ __forceinline__ void cpasync16(uint32_t dst, const void* src) {
    asm volatile("cp.async.cg.shared.global [%0], [%1], 16;" :: "r"(dst), "l"(src));
}
__device__ __forceinline__ void cp_commit() { asm volatile("cp.async.commit_group;" ::: "memory"); }
__device__ __forceinline__ void cp_wait1()  { asm volatile("cp.async.wait_group 1;" ::: "memory"); }

__device__ __forceinline__ void ldsm4(uint32_t* r, uint32_t addr) {
    asm volatile("ldmatrix.sync.aligned.m8n8.x4.shared.b16 {%0,%1,%2,%3}, [%4];"
                 : "=r"(r[0]), "=r"(r[1]), "=r"(r[2]), "=r"(r[3]) : "r"(addr) : "memory");
}
// int8 IMMA: m16n8k32, s32 accumulators
__device__ __forceinline__ void mma16832s8(int* c, const uint32_t* a, const uint32_t* b) {
    asm volatile(
        "mma.sync.aligned.m16n8k32.row.col.s32.s8.s8.s32 "
        "{%0,%1,%2,%3}, {%4,%5,%6,%7}, {%8,%9}, {%0,%1,%2,%3};"
        : "+r"(c[0]), "+r"(c[1]), "+r"(c[2]), "+r"(c[3])
        : "r"(a[0]), "r"(a[1]), "r"(a[2]), "r"(a[3]), "r"(b[0]), "r"(b[1]));
}
__device__ __forceinline__ uint32_t pack4(int b0, int b1, int b2, int b3) {
    return (uint32_t)(b0 & 255) | ((uint32_t)(b1 & 255) << 8) |
           ((uint32_t)(b2 & 255) << 16) | ((uint32_t)(b3 & 255) << 24);
}

// ---------------- prep kernel 1: x -> (hi,lo) int8 planes, tiled + SW128 ----------------
// x16 = rn(x * Q), Q = 32000/rowmax; x16 = 256*hi + lo, hi,lo in [-128,127]
__global__ void convert_x_i8(const float* __restrict__ x) {
    __shared__ float smax[4];
    __shared__ int   ssum[4];
    const int m = blockIdx.x;
    const int t = threadIdx.x;
    const float* xr = x + (size_t)m * IN_F;

    float mx = 0.f;
    for (int i = t; i < IN_F; i += 128) mx = fmaxf(mx, fabsf(xr[i]));
#pragma unroll
    for (int o = 16; o > 0; o >>= 1) mx = fmaxf(mx, __shfl_xor_sync(0xFFFFFFFFu, mx, o));
    if ((t & 31) == 0) smax[t >> 5] = mx;
    __syncthreads();
    const float M = fmaxf(fmaxf(smax[0], smax[1]), fmaxf(smax[2], smax[3]));
    const float Q = 32000.f / M;

    const int mt = m >> 7, r = m & 127;
    const int ktile = t >> 2;                            // (t*32)/128
    const uint32_t rowoff = (uint32_t)r * 128 + (uint32_t)(t & 3) * 32;
    uint8_t* dhi = g_xhi + (size_t)(mt * K_TILES + ktile) * TILE_BYTES;
    uint8_t* dlo = g_xlo + (size_t)(mt * K_TILES + ktile) * TILE_BYTES;
    const float4* src = (const float4*)(xr + t * 32);

    int Tsum = 0;
#pragma unroll
    for (int g = 0; g < 2; g++) {
        uint32_t hw[4], lw[4];
#pragma unroll
        for (int q = 0; q < 4; q++) {
            float4 v = src[g * 4 + q];
            int e0 = __float2int_rn(v.x * Q);
            int e1 = __float2int_rn(v.y * Q);
            int e2 = __float2int_rn(v.z * Q);
            int e3 = __float2int_rn(v.w * Q);
            Tsum += (e0 + e1) + (e2 + e3);
            int h0 = (e0 + 128) >> 8, h1 = (e1 + 128) >> 8, h2 = (e2 + 128) >> 8, h3 = (e3 + 128) >> 8;
            hw[q] = pack4(h0, h1, h2, h3);
            lw[q] = pack4(e0 - (h0 << 8), e1 - (h1 << 8), e2 - (h2 << 8), e3 - (h3 << 8));
        }
        uint32_t off = swz(rowoff + (uint32_t)g * 16);
        *(uint4*)(dhi + off) = make_uint4(hw[0], hw[1], hw[2], hw[3]);
        *(uint4*)(dlo + off) = make_uint4(lw[0], lw[1], lw[2], lw[3]);
    }
#pragma unroll
    for (int o = 16; o > 0; o >>= 1) Tsum += __shfl_xor_sync(0xFFFFFFFFu, Tsum, o);
    if ((t & 31) == 0) ssum[t >> 5] = Tsum;
    __syncthreads();
    if (t == 0) {
        g_T[m] = (float)((ssum[0] + ssum[1]) + (ssum[2] + ssum[3]));
        g_invQ[m] = 1.f / Q;
    }
}

// ---------------- prep kernel 2: packed nibbles (int32 per byte) -> int8 W, tiled + SW128 ----------------
__global__ void dequant_w_i8(const int* __restrict__ wp) {
    const int nt = blockIdx.x / K_TILES;
    const int kt = blockIdx.x % K_TILES;
    const int r  = threadIdx.x; // 0..127 = N row within tile
    const int row = nt * BN + r;
    const uint4* src = (const uint4*)(wp + (size_t)row * (IN_F / 2) + kt * (BKB / 2)); // 64 ints
    uint8_t* dst = g_wq + (size_t)blockIdx.x * TILE_BYTES;
#pragma unroll
    for (int j = 0; j < 8; j++) {
        uint4 qa = src[2 * j];
        uint4 qb = src[2 * j + 1];
        uint32_t e[8] = {qa.x, qa.y, qa.z, qa.w, qb.x, qb.y, qb.z, qb.w};
        uint32_t w[4];
#pragma unroll
        for (int q = 0; q < 4; q++) {
            uint32_t a = e[2 * q], b = e[2 * q + 1];
            w[q] = (a & 15u) | (((a >> 4) & 15u) << 8) | ((b & 15u) << 16) | (((b >> 4) & 15u) << 24);
        }
        *(uint4*)(dst + swz((uint32_t)r * 128 + (uint32_t)j * 16)) = make_uint4(w[0], w[1], w[2], w[3]);
    }
}

// ---------------- main GEMM: int8 IMMA m16n8k32, 3-stage cp.async pipeline ----------------
// 256 threads = 8 warps, 4(M) x 2(N); warp tile 32x64.
// PASS 0: A = hi plane, out = (float)S_hi
// PASS 1: A = lo plane, out = scale/Q * (256*S_hi + S_lo - zero*T)
template <int PASS>
__global__ void __launch_bounds__(256, 2) gemm_i8(float* __restrict__ out,
                                                  const float* __restrict__ scale,
                                                  const float* __restrict__ zero) {
    extern __shared__ __align__(1024) uint8_t sm[];
    uint32_t sb = smem_u32(sm);
    const int tid  = threadIdx.x;
    const int lane = tid & 31;
    const int warp = tid >> 5;
    const int warp_m = warp & 3;
    const int warp_n = warp >> 2;
    const int mt = blockIdx.x % M_TILES;
    const int nt = blockIdx.x / M_TILES;

    const uint8_t* aplane = (PASS == 0) ? g_xhi : g_xlo;
    const uint8_t* ag = aplane + (size_t)(mt * K_TILES) * TILE_BYTES;
    const uint8_t* bg = g_wq   + (size_t)(nt * K_TILES) * TILE_BYTES;

    const uint32_t cp_off = (uint32_t)tid * 64;

    // prologue: stages 0 and 1
#pragma unroll
    for (int s = 0; s < 2; s++) {
        uint32_t dA = sb + s * STAGE_BYTES + cp_off;
        uint32_t dB = dA + TILE_BYTES;
        const uint8_t* srcA = ag + (size_t)s * TILE_BYTES + cp_off;
        const uint8_t* srcB = bg + (size_t)s * TILE_BYTES + cp_off;
#pragma unroll
        for (int j = 0; j < 4; j++) {
            cpasync16(dA + j * 16, srcA + j * 16);
            cpasync16(dB + j * 16, srcB + j * 16);
        }
        cp_commit();
    }

    // per-lane ldmatrix address components (SW128)
    const int a_row = warp_m * 32 + (lane & 15);
    const uint32_t a_xor = (uint32_t)((a_row & 7) << 4);
    const uint32_t a_cb  = (uint32_t)((lane >> 4) << 4);
    const int b_row = warp_n * 64 + (lane & 7) + ((lane >> 4) << 3);
    const uint32_t b_xor = (uint32_t)((b_row & 7) << 4);
    const uint32_t b_cb  = (uint32_t)((lane & 8) << 1);

    int acc[2][8][4];
#pragma unroll
    for (int i = 0; i < 2; i++)
#pragma unroll
        for (int j = 0; j < 8; j++)
#pragma unroll
            for (int q = 0; q < 4; q++) acc[i][j][q] = 0;

#pragma unroll 1
    for (int kt = 0; kt < K_TILES; kt++) {
        cp_wait1();
        __syncthreads();

        if (kt + 2 < K_TILES) {
            int s = (kt + 2) % STAGES;
            uint32_t dA = sb + s * STAGE_BYTES + cp_off;
            uint32_t dB = dA + TILE_BYTES;
            const uint8_t* srcA = ag + (size_t)(kt + 2) * TILE_BYTES + cp_off;
            const uint8_t* srcB = bg + (size_t)(kt + 2) * TILE_BYTES + cp_off;
#pragma unroll
            for (int j = 0; j < 4; j++) {
                cpasync16(dA + j * 16, srcA + j * 16);
                cpasync16(dB + j * 16, srcB + j * 16);
            }
        }
        cp_commit();

        uint32_t sA = sb + (kt % STAGES) * STAGE_BYTES;
        uint32_t sB = sA + TILE_BYTES;
#pragma unroll
        for (int k32 = 0; k32 < 4; k32++) {
            uint32_t kc = (uint32_t)(k32 * 32);       // 32 bytes = K32 int8
            uint32_t a[2][4];
#pragma unroll
            for (int mtile = 0; mtile < 2; mtile++) {
                uint32_t addr = sA + (uint32_t)(a_row + 16 * mtile) * 128 + ((kc + a_cb) ^ a_xor);
                ldsm4(a[mtile], addr);
            }
#pragma unroll
            for (int p = 0; p < 4; p++) {
                uint32_t bb[4];
                uint32_t addr = sB + (uint32_t)(b_row + 16 * p) * 128 + ((kc + b_cb) ^ b_xor);
                ldsm4(bb, addr);
                mma16832s8(acc[0][2 * p + 0], a[0], bb + 0);
                mma16832s8(acc[0][2 * p + 1], a[0], bb + 2);
                mma16832s8(acc[1][2 * p + 0], a[1], bb + 0);
                mma16832s8(acc[1][2 * p + 1], a[1], bb + 2);
            }
        }
    }

    // epilogue
    const int m_lo = mt * BM + warp_m * 32 + (lane >> 2);
    const int n_base = nt * BN + warp_n * 64 + 2 * (lane & 3);
#pragma unroll
    for (int mtile = 0; mtile < 2; mtile++) {
        int m0 = m_lo + 16 * mtile;
        float* o0 = out + (size_t)m0 * OUT_F + n_base;
        float* o1 = o0 + (size_t)8 * OUT_F;
        if (PASS == 0) {
#pragma unroll
            for (int p = 0; p < 8; p++) {
                float2 v0, v1;
                v0.x = (float)acc[mtile][p][0];
                v0.y = (float)acc[mtile][p][1];
                v1.x = (float)acc[mtile][p][2];
                v1.y = (float)acc[mtile][p][3];
                *(float2*)(o0 + 8 * p) = v0;
                *(float2*)(o1 + 8 * p) = v1;
            }
        } else {
            float iq0 = g_invQ[m0],     T0 = g_T[m0];
            float iq1 = g_invQ[m0 + 8], T1 = g_T[m0 + 8];
#pragma unroll
            for (int p = 0; p < 8; p++) {
                int n = n_base + 8 * p;
                float sc0 = scale[n], sc1 = scale[n + 1];
                float z0 = zero[n],  z1 = zero[n + 1];
                float2 pr0 = *(float2*)(o0 + 8 * p);
                float2 pr1 = *(float2*)(o1 + 8 * p);
                float2 v0, v1;
                v0.x = sc0 * iq0 * (256.f * pr0.x + (float)acc[mtile][p][0] - z0 * T0);
                v0.y = sc1 * iq0 * (256.f * pr0.y + (float)acc[mtile][p][1] - z1 * T0);
                v1.x = sc0 * iq1 * (256.f * pr1.x + (float)acc[mtile][p][2] - z0 * T1);
                v1.y = sc1 * iq1 * (256.f * pr1.y + (float)acc[mtile][p][3] - z1 * T1);
                *(float2*)(o0 + 8 * p) = v0;
                *(float2*)(o1 + 8 * p) = v1;
            }
        }
    }
}

// ---------------- launch ----------------
extern "C" void kernel_launch(void* const* d_in, const int* in_sizes, int n_in,
                              void* d_out, int out_size) {
    const float* x     = (const float*)d_in[0];
    const int*   wpack = (const int*)d_in[1];   // uint8 promoted to int32 by harness
    const float* scale = (const float*)d_in[2];
    const float* zero  = (const float*)d_in[3];
    float*       out   = (float*)d_out;

    cudaFuncSetAttribute(gemm_i8<0>, cudaFuncAttributeMaxDynamicSharedMemorySize, SMEM_BYTES);
    cudaFuncSetAttribute(gemm_i8<1>, cudaFuncAttributeMaxDynamicSharedMemorySize, SMEM_BYTES);

    convert_x_i8<<<TOKENS, 128>>>(x);
    dequant_w_i8<<<N_TILES * K_TILES, 128>>>(wpack);
    gemm_i8<0><<<M_TILES * N_TILES, 256, SMEM_BYTES>>>(out, scale, zero);
    gemm_i8<1><<<M_TILES * N_TILES, 256, SMEM_BYTES>>>(out, scale, zero);
}

// round 9
// speedup vs baseline: 4.0758x; 4.0758x over previous
#include <cuda_runtime.h>
#include <cuda_fp16.h>
#include <cstdint>

// ---------------- problem constants ----------------
static constexpr int TOKENS = 4096;
static constexpr int IN_F   = 4096;
static constexpr int OUT_F  = 11008;

static constexpr int BM = 128;
static constexpr int BN = 128;
static constexpr int BK = 64;          // 64 fp16 = 128 bytes per row (SW128 atom row)
static constexpr int STAGES = 3;

static constexpr int M_TILES = TOKENS / BM;   // 32
static constexpr int N_TILES = OUT_F / BN;    // 86
static constexpr int K_TILES = IN_F / BK;     // 64

static constexpr int TILE_BYTES = 128 * BK * 2;     // 16384 (A tile == B tile)
static constexpr int STAGE_BYTES = 2 * TILE_BYTES;  // 32768
static constexpr int SMEM_BYTES = STAGES * STAGE_BYTES; // 98304

static constexpr int X_BLOCKS = M_TILES * K_TILES;  // 2048
static constexpr int W_BLOCKS = N_TILES * K_TILES;  // 5504

// ---------------- device scratch (no cudaMalloc allowed) ----------------
__device__ __align__(1024) uint8_t g_xbuf[(size_t)M_TILES * K_TILES * TILE_BYTES]; // 32 MB fp16 tiles, SW128
__device__ __align__(1024) uint8_t g_wbuf[(size_t)N_TILES * K_TILES * TILE_BYTES]; // 88 MB fp16 tiles, SW128

// ---------------- helpers ----------------
__device__ __forceinline__ uint32_t smem_u32(const void* p) {
    uint32_t a;
    asm("{ .reg .u64 t; cvta.to.shared.u64 t, %1; cvt.u32.u64 %0, t; }" : "=r"(a) : "l"(p));
    return a;
}
__device__ __forceinline__ uint32_t h2u(__half2 h) { uint32_t u; __builtin_memcpy(&u, &h, 4); return u; }
__device__ __forceinline__ uint32_t swz(uint32_t off) { return off ^ ((off >> 3) & 0x70); }

__device__ __forceinline__ void cpasync16(uint32_t dst, const void* src) {
    asm volatile("cp.async.cg.shared.global [%0], [%1], 16;" :: "r"(dst), "l"(src));
}
__device__ __forceinline__ void cp_commit() { asm volatile("cp.async.commit_group;" ::: "memory"); }
__device__ __forceinline__ void cp_wait1()  { asm volatile("cp.async.wait_group 1;" ::: "memory"); }

__device__ __forceinline__ void ldsm4(uint32_t* r, uint32_t addr) {
    asm volatile("ldmatrix.sync.aligned.m8n8.x4.shared.b16 {%0,%1,%2,%3}, [%4];"
                 : "=r"(r[0]), "=r"(r[1]), "=r"(r[2]), "=r"(r[3]) : "r"(addr) : "memory");
}
__device__ __forceinline__ void mma16816(float* c, const uint32_t* a, const uint32_t* b) {
    asm volatile(
        "mma.sync.aligned.m16n8k16.row.col.f32.f16.f16.f32 "
        "{%0,%1,%2,%3}, {%4,%5,%6,%7}, {%8,%9}, {%0,%1,%2,%3};"
        : "+f"(c[0]), "+f"(c[1]), "+f"(c[2]), "+f"(c[3])
        : "r"(a[0]), "r"(a[1]), "r"(a[2]), "r"(a[3]), "r"(b[0]), "r"(b[1]));
}

// ---------------- merged prep kernel ----------------
// blocks [0, X_BLOCKS):          x fp32 -> fp16, tiled + SW128
// blocks [X_BLOCKS, +W_BLOCKS):  packed nibbles (int32 per byte) -> fp16 dequant W, tiled + SW128
__global__ void prep_kernel(const float* __restrict__ x,
                            const int* __restrict__ wp,
                            const float* __restrict__ scale,
                            const float* __restrict__ zero) {
    const int blk = blockIdx.x;
    const int r = threadIdx.x; // 0..127 = row within tile
    if (blk < X_BLOCKS) {
        const int mt = blk / K_TILES;
        const int kt = blk % K_TILES;
        const float4* src = (const float4*)(x + (size_t)(mt * BM + r) * IN_F + kt * BK);
        uint8_t* dst = g_xbuf + (size_t)blk * TILE_BYTES;
#pragma unroll
        for (int g = 0; g < 8; g++) {
            float4 a = src[2 * g];
            float4 b = src[2 * g + 1];
            uint4 v;
            v.x = h2u(__floats2half2_rn(a.x, a.y));
            v.y = h2u(__floats2half2_rn(a.z, a.w));
            v.z = h2u(__floats2half2_rn(b.x, b.y));
            v.w = h2u(__floats2half2_rn(b.z, b.w));
            uint32_t off = (uint32_t)(r * 128 + g * 16);
            *(uint4*)(dst + swz(off)) = v;
        }
    } else {
        const int wblk = blk - X_BLOCKS;
        const int nt = wblk / K_TILES;
        const int kt = wblk % K_TILES;
        const int row = nt * BN + r;
        const float s = scale[row];
        const float b = -zero[row] * s;
        const uint4* src = (const uint4*)(wp + (size_t)row * (IN_F / 2) + kt * (BK / 2)); // 32 ints
        uint8_t* dst = g_wbuf + (size_t)wblk * TILE_BYTES;
#pragma unroll
        for (int j = 0; j < 8; j++) {
            uint4 q = src[j];
            uint32_t e[4] = {q.x, q.y, q.z, q.w};
            uint32_t h[4];
#pragma unroll
            for (int t = 0; t < 4; t++) {
                float v0 = fmaf((float)(e[t] & 15u), s, b);          // even k
                float v1 = fmaf((float)((e[t] >> 4) & 15u), s, b);   // odd k
                h[t] = h2u(__floats2half2_rn(v0, v1));
            }
            uint4 v = make_uint4(h[0], h[1], h[2], h[3]);
            uint32_t off = (uint32_t)(r * 128 + j * 16);
            *(uint4*)(dst + swz(off)) = v;
        }
    }
}

// ---------------- main GEMM: mma.sync (HMMA) + cp.async 3-stage pipeline ----------------
// 256 threads = 8 warps in a 4(M) x 2(N) grid; warp tile 32x64.
// A-fragment loads are software-pipelined one k16 step ahead.
__global__ void __launch_bounds__(256, 2) gemm_kernel(float* __restrict__ out) {
    extern __shared__ __align__(1024) uint8_t sm[];
    uint32_t sb = smem_u32(sm);
    const int tid  = threadIdx.x;
    const int lane = tid & 31;
    const int warp = tid >> 5;
    const int warp_m = warp & 3;
    const int warp_n = warp >> 2;
    const int mt = blockIdx.x % M_TILES;
    const int nt = blockIdx.x / M_TILES;

    const uint8_t* ag = g_xbuf + (size_t)(mt * K_TILES) * TILE_BYTES;
    const uint8_t* bg = g_wbuf + (size_t)(nt * K_TILES) * TILE_BYTES;

    const uint32_t cp_off = (uint32_t)tid * 64;

    // prologue: stages 0 and 1
#pragma unroll
    for (int s = 0; s < 2; s++) {
        uint32_t dA = sb + s * STAGE_BYTES + cp_off;
        uint32_t dB = dA + TILE_BYTES;
        const uint8_t* srcA = ag + (size_t)s * TILE_BYTES + cp_off;
        const uint8_t* srcB = bg + (size_t)s * TILE_BYTES + cp_off;
#pragma unroll
        for (int j = 0; j < 4; j++) {
            cpasync16(dA + j * 16, srcA + j * 16);
            cpasync16(dB + j * 16, srcB + j * 16);
        }
        cp_commit();
    }

    // per-lane ldmatrix address components (SW128: swz(r*128+c) = r*128 + (c ^ ((r&7)<<4)))
    const int a_row = warp_m * 32 + (lane & 15);          // + 16*mtile
    const uint32_t a_xor = (uint32_t)((a_row & 7) << 4);
    const uint32_t a_cb  = (uint32_t)((lane >> 4) << 4);  // 0 or 16
    const int b_row = warp_n * 64 + (lane & 7) + ((lane >> 4) << 3);  // + 16*p
    const uint32_t b_xor = (uint32_t)((b_row & 7) << 4);
    const uint32_t b_cb  = (uint32_t)((lane & 8) << 1);   // 0 or 16

    // A ldmatrix base offsets (per mtile), add stage base + k-column each use
    const uint32_t aoff0 = (uint32_t)(a_row +  0) * 128;
    const uint32_t aoff1 = (uint32_t)(a_row + 16) * 128;

    float acc[2][8][4];
#pragma unroll
    for (int i = 0; i < 2; i++)
#pragma unroll
        for (int j = 0; j < 8; j++)
#pragma unroll
            for (int q = 0; q < 4; q++) acc[i][j][q] = 0.f;

#pragma unroll 1
    for (int kt = 0; kt < K_TILES; kt++) {
        cp_wait1();
        __syncthreads();

        // issue stage kt+2
        if (kt + 2 < K_TILES) {
            int s = (kt + 2) % STAGES;
            uint32_t dA = sb + s * STAGE_BYTES + cp_off;
            uint32_t dB = dA + TILE_BYTES;
            const uint8_t* srcA = ag + (size_t)(kt + 2) * TILE_BYTES + cp_off;
            const uint8_t* srcB = bg + (size_t)(kt + 2) * TILE_BYTES + cp_off;
#pragma unroll
            for (int j = 0; j < 4; j++) {
                cpasync16(dA + j * 16, srcA + j * 16);
                cpasync16(dB + j * 16, srcB + j * 16);
            }
        }
        cp_commit();

        // compute stage kt, A frags pipelined one k16 ahead
        uint32_t sA = sb + (kt % STAGES) * STAGE_BYTES;
        uint32_t sB = sA + TILE_BYTES;

        uint32_t acur[2][4], anext[2][4];
        {
            uint32_t kc0 = a_cb ^ a_xor;   // k16 = 0
            ldsm4(acur[0], sA + aoff0 + kc0);
            ldsm4(acur[1], sA + aoff1 + kc0);
        }
#pragma unroll
        for (int k16 = 0; k16 < 4; k16++) {
            if (k16 < 3) {
                uint32_t kcn = (uint32_t)((k16 + 1) * 32);
                uint32_t kn = (kcn + a_cb) ^ a_xor;
                ldsm4(anext[0], sA + aoff0 + kn);
                ldsm4(anext[1], sA + aoff1 + kn);
            }
            uint32_t kc = (uint32_t)(k16 * 32);
#pragma unroll
            for (int p = 0; p < 4; p++) {
                uint32_t bb[4];
                uint32_t addr = sB + (uint32_t)(b_row + 16 * p) * 128 + ((kc + b_cb) ^ b_xor);
                ldsm4(bb, addr);
                mma16816(acc[0][2 * p + 0], acur[0], bb + 0);
                mma16816(acc[0][2 * p + 1], acur[0], bb + 2);
                mma16816(acc[1][2 * p + 0], acur[1], bb + 0);
                mma16816(acc[1][2 * p + 1], acur[1], bb + 2);
            }
            if (k16 < 3) {
#pragma unroll
                for (int i = 0; i < 2; i++)
#pragma unroll
                    for (int q = 0; q < 4; q++) acur[i][q] = anext[i][q];
            }
        }
    }

    // epilogue: plain accumulator stores (scale/zero already folded into W)
    const int m_lo = mt * BM + warp_m * 32 + (lane >> 2);
    const int n_lo = nt * BN + warp_n * 64 + 2 * (lane & 3);
#pragma unroll
    for (int mtile = 0; mtile < 2; mtile++) {
        int m0 = m_lo + 16 * mtile;
        float* o0 = out + (size_t)m0 * OUT_F + n_lo;
        float* o1 = o0 + (size_t)8 * OUT_F;
#pragma unroll
        for (int p = 0; p < 8; p++) {
            float2 v0, v1;
            v0.x = acc[mtile][p][0];
            v0.y = acc[mtile][p][1];
            v1.x = acc[mtile][p][2];
            v1.y = acc[mtile][p][3];
            *(float2*)(o0 + 8 * p) = v0;
            *(float2*)(o1 + 8 * p) = v1;
        }
    }
}

// ---------------- launch ----------------
extern "C" void kernel_launch(void* const* d_in, const int* in_sizes, int n_in,
                              void* d_out, int out_size) {
    const float* x     = (const float*)d_in[0];
    const int*   wpack = (const int*)d_in[1];   // uint8 promoted to int32 by harness
    const float* scale = (const float*)d_in[2];
    const float* zero  = (const float*)d_in[3];
    float*       out   = (float*)d_out;

    cudaFuncSetAttribute(gemm_kernel, cudaFuncAttributeMaxDynamicSharedMemorySize, SMEM_BYTES);

    prep_kernel<<<X_BLOCKS + W_BLOCKS, 128>>>(x, wpack, scale, zero);
    gemm_kernel<<<M_TILES * N_TILES, 256, SMEM_BYTES>>>(out);
}